// round 5
// baseline (speedup 1.0000x reference)
#include <cuda_runtime.h>

// SigmoidFlow: B=2048, D=512, NDIM=16
// out[0..B*D) = xnew ; out[B*D..B*D+B) = logdet
//
// R5: single-wave, 2 rows per 256-thread CTA (grid=B/2, 7 CTAs/SM => all
// resident, 56 warps/SM). Default cache policy (no .cs - it reduced HBM
// throughput in R2-R4). Math = R2: single-rcp cofactor sigmoids, 3 logs
// per element.

#define TPB 256

__device__ __forceinline__ float fast_rcp(float v) {
    float r; asm("rcp.approx.f32 %0, %1;" : "=f"(r) : "f"(v)); return r;
}

__device__ __forceinline__ void sf_compute(float4 av, float4 bv, float4 wv, float xv,
                                           float& Wl, float& Sl, float& Dl)
{
    float a_[4] = {av.x, av.y, av.z, av.w};
    float b_[4] = {bv.x, bv.y, bv.z, bv.w};
    float wl[4] = {wv.x, wv.y, wv.z, wv.w};

    float asp[4], t[4], onet[4], ew[4];
    #pragma unroll
    for (int j = 0; j < 4; ++j) {
        float ea  = __expf(a_[j]);
        asp[j]    = __logf(1.0f + ea);            // softplus
        float pre = fmaf(asp[j], xv, b_[j]);
        t[j]      = __expf(-pre);
        onet[j]   = 1.0f + t[j];
        ew[j]     = __expf(wl[j]);
    }
    float p01 = onet[0] * onet[1];
    float p23 = onet[2] * onet[3];
    float iP  = fast_rcp(p01 * p23);
    float h0  = (onet[1] * p23) * iP;             // sigm_0
    float h1  = (onet[0] * p23) * iP;
    float h2  = (p01 * onet[3]) * iP;
    float h3  = (p01 * onet[2]) * iP;

    Wl = (ew[0] + ew[1]) + (ew[2] + ew[3]);
    Sl = fmaf(ew[3], h3, fmaf(ew[2], h2, fmaf(ew[1], h1, ew[0] * h0)));
    float d0 = (ew[0] * asp[0]) * (t[0] * h0 * h0);
    float d1 = (ew[1] * asp[1]) * (t[1] * h1 * h1);
    float d2 = (ew[2] * asp[2]) * (t[2] * h2 * h2);
    float d3 = (ew[3] * asp[3]) * (t[3] * h3 * h3);
    Dl = (d0 + d1) + (d2 + d3);
}

__global__ __launch_bounds__(TPB, 7)
void sf_kernel(const float* __restrict__ x,
               const float* __restrict__ logdet_in,
               const float* __restrict__ dsp,
               float* __restrict__ out,
               int B, int D)
{
    const int tid  = threadIdx.x;
    const int half = tid >> 7;                   // 0/1: which row this half handles
    const int htid = tid & 127;
    const int lane = tid & 31;
    const int q    = lane & 3;                   // component group
    const int e_in_half = ((htid >> 5) << 3) + (lane >> 2);   // 0..31

    const int b = blockIdx.x * 2 + half;
    const bool row_ok = (b < B);

    const float ONE_MD = 1.0f - 1e-6f;
    const float HALF_D = 0.5e-6f;
    const float LOG1MD = -1.0000005e-6f;

    __shared__ float s_part[TPB / 32];           // 8 warp partials (4 per half)

    float acc = 0.0f;

    const int niter = (D + 31) / 32;
    if (row_ok) {
        const float*  xrow = x + (long long)b * D;
        const float4* prow = (const float4*)(dsp + (long long)b * D * 48);

        for (int it = 0; it < niter; ++it) {
            const int d = it * 32 + e_in_half;
            if (d < D) {
                const float4* p = prow + (long long)d * 12;
                const float4 av = __ldg(p + q);
                const float4 bv = __ldg(p + 4 + q);
                const float4 wv = __ldg(p + 8 + q);
                const float  xv = __ldg(xrow + d);

                float Wl, Sl, Dl;
                sf_compute(av, bv, wv, xv, Wl, Sl, Dl);

                // reduce (W,S,D) across the 4-lane group
                Wl += __shfl_xor_sync(0xffffffffu, Wl, 1);
                Sl += __shfl_xor_sync(0xffffffffu, Sl, 1);
                Dl += __shfl_xor_sync(0xffffffffu, Dl, 1);
                Wl += __shfl_xor_sync(0xffffffffu, Wl, 2);
                Sl += __shfl_xor_sync(0xffffffffu, Sl, 2);
                Dl += __shfl_xor_sync(0xffffffffu, Dl, 2);

                const float hw = HALF_D * Wl;
                const float N1 = fmaf(ONE_MD, Sl, hw);
                const float N2 = fmaf(ONE_MD, Wl - Sl, hw);
                const float l1 = __logf(N1);
                const float l2 = __logf(N2);
                const float l3 = __logf(Dl * Wl);

                if (q == 0) out[(long long)b * D + d] = l1 - l2;   // xnew
                acc += l3 - l1 - l2 + LOG1MD;                      // replicated x4
            }
        }
    }

    // per-warp reduction (warps are entirely within one half)
    #pragma unroll
    for (int m = 16; m >= 1; m >>= 1)
        acc += __shfl_xor_sync(0xffffffffu, acc, m);
    if (lane == 0) s_part[tid >> 5] = acc;
    __syncthreads();

    if (htid == 0 && row_ok) {
        const int base = half * 4;
        float v = (s_part[base] + s_part[base + 1]) +
                  (s_part[base + 2] + s_part[base + 3]);
        out[(long long)B * D + b] = 0.25f * v + __ldg(logdet_in + b);
    }
}

extern "C" void kernel_launch(void* const* d_in, const int* in_sizes, int n_in,
                              void* d_out, int out_size)
{
    const float* x   = (const float*)d_in[0];   // (B, D)
    const float* ld  = (const float*)d_in[1];   // (B,)
    const float* dsp = (const float*)d_in[2];   // (B, D, 48)
    float* out = (float*)d_out;

    const int B = in_sizes[1];
    const int D = in_sizes[0] / B;

    const int grid = (B + 1) / 2;
    sf_kernel<<<grid, TPB>>>(x, ld, dsp, out, B, D);
}

// round 6
// speedup vs baseline: 1.0032x; 1.0032x over previous
#include <cuda_runtime.h>

// SigmoidFlow: B=2048, D=512, NDIM=16
// out[0..B*D) = xnew ; out[B*D..B*D+B) = logdet
//
// R6: R4 launch shape (TPB=128, one row per CTA, single wave, 32 regs) +
// L2::256B fetch promotion on the dsparams loads. Each LDG.128 alone touches
// 8 disjoint 64B half-lines (192B element stride); 256B promotion pulls the
// sibling sectors that the partner loads consume, improving DRAM bursts with
// zero waste. Math = R2 (single-rcp cofactor, 3 logs/element).

#define TPB 128

__device__ __forceinline__ float fast_rcp(float v) {
    float r; asm("rcp.approx.f32 %0, %1;" : "=f"(r) : "f"(v)); return r;
}

__device__ __forceinline__ float4 ldg256(const float4* p) {
    float4 v;
    asm("ld.global.nc.L2::256B.v4.f32 {%0,%1,%2,%3}, [%4];"
        : "=f"(v.x), "=f"(v.y), "=f"(v.z), "=f"(v.w) : "l"(p));
    return v;
}

__device__ __forceinline__ void sf_compute(float4 av, float4 bv, float4 wv, float xv,
                                           float& Wl, float& Sl, float& Dl)
{
    float a_[4] = {av.x, av.y, av.z, av.w};
    float b_[4] = {bv.x, bv.y, bv.z, bv.w};
    float wl[4] = {wv.x, wv.y, wv.z, wv.w};

    float asp[4], t[4], onet[4], ew[4];
    #pragma unroll
    for (int j = 0; j < 4; ++j) {
        float ea  = __expf(a_[j]);
        asp[j]    = __logf(1.0f + ea);            // softplus
        float pre = fmaf(asp[j], xv, b_[j]);
        t[j]      = __expf(-pre);
        onet[j]   = 1.0f + t[j];
        ew[j]     = __expf(wl[j]);
    }
    float p01 = onet[0] * onet[1];
    float p23 = onet[2] * onet[3];
    float iP  = fast_rcp(p01 * p23);
    float h0  = (onet[1] * p23) * iP;             // sigm_0
    float h1  = (onet[0] * p23) * iP;
    float h2  = (p01 * onet[3]) * iP;
    float h3  = (p01 * onet[2]) * iP;

    Wl = (ew[0] + ew[1]) + (ew[2] + ew[3]);
    Sl = fmaf(ew[3], h3, fmaf(ew[2], h2, fmaf(ew[1], h1, ew[0] * h0)));
    float d0 = (ew[0] * asp[0]) * (t[0] * h0 * h0);
    float d1 = (ew[1] * asp[1]) * (t[1] * h1 * h1);
    float d2 = (ew[2] * asp[2]) * (t[2] * h2 * h2);
    float d3 = (ew[3] * asp[3]) * (t[3] * h3 * h3);
    Dl = (d0 + d1) + (d2 + d3);
}

// D must be a multiple of 32 (guard-free loop).
__global__ __launch_bounds__(TPB, 16)
void sf_kernel(const float* __restrict__ x,
               const float* __restrict__ logdet_in,
               const float* __restrict__ dsp,
               float* __restrict__ out,
               int B, int D)
{
    const int b    = blockIdx.x;
    const int tid  = threadIdx.x;
    const int lane = tid & 31;
    const int wid  = tid >> 5;                     // 0..3
    const int q    = lane & 3;                     // component group
    const int e0   = wid * 8 + (lane >> 2);        // 0..31

    const float ONE_MD = 1.0f - 1e-6f;
    const float HALF_D = 0.5e-6f;
    const float LOG1MD = -1.0000005e-6f;

    __shared__ float s_part[TPB / 32];

    const float*  xrow = x + (long long)b * D;
    const float4* prow = (const float4*)(dsp + (long long)b * D * 48);
    float*        orow = out + (long long)b * D;

    float acc = 0.0f;

    for (int d = e0; d < D; d += 32) {
        const float4* p = prow + (long long)d * 12;
        const float4 av = ldg256(p + q);
        const float4 bv = ldg256(p + 4 + q);
        const float4 wv = ldg256(p + 8 + q);
        const float  xv = __ldg(xrow + d);

        float Wl, Sl, Dl;
        sf_compute(av, bv, wv, xv, Wl, Sl, Dl);

        // reduce (W,S,D) across the 4-lane group
        Wl += __shfl_xor_sync(0xffffffffu, Wl, 1);
        Sl += __shfl_xor_sync(0xffffffffu, Sl, 1);
        Dl += __shfl_xor_sync(0xffffffffu, Dl, 1);
        Wl += __shfl_xor_sync(0xffffffffu, Wl, 2);
        Sl += __shfl_xor_sync(0xffffffffu, Sl, 2);
        Dl += __shfl_xor_sync(0xffffffffu, Dl, 2);

        const float hw = HALF_D * Wl;
        const float N1 = fmaf(ONE_MD, Sl, hw);
        const float N2 = fmaf(ONE_MD, Wl - Sl, hw);
        const float l1 = __logf(N1);
        const float l2 = __logf(N2);
        const float l3 = __logf(Dl * Wl);

        if (q == 0) orow[d] = l1 - l2;             // xnew
        acc += l3 - l1 - l2 + LOG1MD;              // replicated x4
    }

    // warp + block reduction (each element counted 4x -> scale 0.25)
    #pragma unroll
    for (int m = 16; m >= 1; m >>= 1)
        acc += __shfl_xor_sync(0xffffffffu, acc, m);
    if (lane == 0) s_part[wid] = acc;
    __syncthreads();

    if (tid == 0) {
        float v = (s_part[0] + s_part[1]) + (s_part[2] + s_part[3]);
        out[(long long)B * D + b] = 0.25f * v + __ldg(logdet_in + b);
    }
}

// Generic fallback for D not a multiple of 32.
__global__ __launch_bounds__(TPB)
void sf_kernel_gen(const float* __restrict__ x,
                   const float* __restrict__ logdet_in,
                   const float* __restrict__ dsp,
                   float* __restrict__ out,
                   int B, int D)
{
    const int b    = blockIdx.x;
    const int tid  = threadIdx.x;
    const int lane = tid & 31;
    const int wid  = tid >> 5;
    const int q    = lane & 3;
    const int e0   = wid * 8 + (lane >> 2);

    const float ONE_MD = 1.0f - 1e-6f;
    const float HALF_D = 0.5e-6f;
    const float LOG1MD = -1.0000005e-6f;

    __shared__ float s_part[TPB / 32];
    float acc = 0.0f;

    const int niter = (D + 31) / 32;
    for (int it = 0; it < niter; ++it) {
        const int d = it * 32 + e0;
        if (d < D) {
            const long long idx = (long long)b * D + d;
            const float4* p = (const float4*)(dsp + idx * 48);
            const float4 av = __ldg(p + q);
            const float4 bv = __ldg(p + 4 + q);
            const float4 wv = __ldg(p + 8 + q);
            const float  xv = __ldg(x + idx);

            float Wl, Sl, Dl;
            sf_compute(av, bv, wv, xv, Wl, Sl, Dl);

            Wl += __shfl_xor_sync(0xffffffffu, Wl, 1);
            Sl += __shfl_xor_sync(0xffffffffu, Sl, 1);
            Dl += __shfl_xor_sync(0xffffffffu, Dl, 1);
            Wl += __shfl_xor_sync(0xffffffffu, Wl, 2);
            Sl += __shfl_xor_sync(0xffffffffu, Sl, 2);
            Dl += __shfl_xor_sync(0xffffffffu, Dl, 2);

            const float hw = HALF_D * Wl;
            const float N1 = fmaf(ONE_MD, Sl, hw);
            const float N2 = fmaf(ONE_MD, Wl - Sl, hw);
            const float l1 = __logf(N1);
            const float l2 = __logf(N2);
            const float l3 = __logf(Dl * Wl);

            if (q == 0) out[idx] = l1 - l2;
            acc += l3 - l1 - l2 + LOG1MD;
        }
    }

    #pragma unroll
    for (int m = 16; m >= 1; m >>= 1)
        acc += __shfl_xor_sync(0xffffffffu, acc, m);
    if (lane == 0) s_part[wid] = acc;
    __syncthreads();

    if (tid == 0) {
        float v = (s_part[0] + s_part[1]) + (s_part[2] + s_part[3]);
        out[(long long)B * D + b] = 0.25f * v + __ldg(logdet_in + b);
    }
}

extern "C" void kernel_launch(void* const* d_in, const int* in_sizes, int n_in,
                              void* d_out, int out_size)
{
    const float* x   = (const float*)d_in[0];   // (B, D)
    const float* ld  = (const float*)d_in[1];   // (B,)
    const float* dsp = (const float*)d_in[2];   // (B, D, 48)
    float* out = (float*)d_out;

    const int B = in_sizes[1];
    const int D = in_sizes[0] / B;

    if ((D & 31) == 0)
        sf_kernel<<<B, TPB>>>(x, ld, dsp, out, B, D);
    else
        sf_kernel_gen<<<B, TPB>>>(x, ld, dsp, out, B, D);
}